// round 4
// baseline (speedup 1.0000x reference)
#include <cuda_runtime.h>

// HH_Synaptic: semi-implicit Hodgkin-Huxley + synapse integrator.
// z: (B=16, N=2000, L=1024) float32.  out: sigmoid((V - VT)/KP), same shape.
// Round 4: 4 independent chains per thread (4-way ILP inside the serial
// recurrence), float4 coalesced z loads / out stores.
// 4096 threads = 128 blocks x 32; thread t -> b = t>>8, l = (t&255)*4.

#define N_DIM 2000
#define LQ    256        // L/4 float4 groups per row
#define PF    4          // z prefetch distance (steps)
#define CH    4          // chains per thread

__device__ __forceinline__ float ex2f_(float x) {
    float r; asm("ex2.approx.f32 %0, %1;" : "=f"(r) : "f"(x)); return r;
}
__device__ __forceinline__ float rcpf_(float x) {
    float r; asm("rcp.approx.f32 %0, %1;" : "=f"(r) : "f"(x)); return r;
}

__global__ __launch_bounds__(32, 1)
void hh_synaptic_kernel(const float4* __restrict__ z, float4* __restrict__ out) {
    const int t  = blockIdx.x * blockDim.x + threadIdx.x;   // 0 .. 4095
    const int b  = t >> 8;
    const int gl = t & 255;

    const float4* zp = z   + (size_t)b * (N_DIM * LQ) + gl;
    float4*       op = out + (size_t)b * (N_DIM * LQ) + gl;

    const float LOG2E = 1.4426950408889634f;
    const float c9    = LOG2E / 9.0f;
    const float c12   = LOG2E / 12.0f;
    const float cAH   = 0.25f * expf(-56.0f / 12.0f);
    const float cSIG  = LOG2E / 3.0f;

    // State (4 independent chains)
    float V[CH], m[CH], n[CH], h[CH], y[CH];
    #pragma unroll
    for (int c = 0; c < CH; ++c) { V[c] = -70.0f; m[c] = 0.0f; n[c] = 0.0f; h[c] = 1.0f; y[c] = 0.0f; }

    // k = 0 output: sigmoid((-70+20)/3) — same for all chains
    {
        float e  = ex2f_(-(-70.0f + 20.0f) * cSIG);
        float s0 = rcpf_(1.0f + e);
        float4 o; o.x = s0; o.y = s0; o.z = s0; o.w = s0;
        op[0] = o;
    }

    // z prefetch ring (float4): step k consumes z row (k-1)
    float4 zbuf[PF];
    #pragma unroll
    for (int j = 0; j < PF; ++j)
        zbuf[j] = __ldg(zp + (size_t)j * LQ);

    float4* ol = op + LQ;

    #pragma unroll 1
    for (int k = 1; k < N_DIM; ++k) {
        float4 z4 = zbuf[0];
        #pragma unroll
        for (int j = 0; j < PF - 1; ++j) zbuf[j] = zbuf[j + 1];
        int pidx = min(k - 1 + PF, N_DIM - 1);     // clamped slots never consumed
        zbuf[PF - 1] = __ldg(zp + (size_t)pidx * LQ);

        float zc[CH] = { z4.x, z4.y, z4.z, z4.w };
        float sg[CH];

        #pragma unroll
        for (int c = 0; c < CH; ++c) {
            // ---- synapse update (independent of V path) ----
            float pY = fmaf(0.01f, zc[c], 0.001f);           // DT/2*(z + A_R)
            float yn = fmaf(zc[c], 0.02f, fmaf(-pY, y[c], y[c])) * rcpf_(1.0f + pY);

            // ---- implicit V update ----
            float pow1 = 40.0f * (m[c] * m[c] * m[c]) * h[c];   // GNA*m^3*h
            float n2   = n[c] * n[c];
            float pow2 = 35.0f * (n2 * n2);                      // GK*n^4
            float G    = 0.01f * (pow1 + pow2 + (0.3f + y[c]));
            float E    = fmaf(pow1, 55.0f, fmaf(pow2, -77.0f, -19.5f));
            float base = fmaf(0.02f, E, V[c] + 0.02f);           // V + DT*(E+IAPP)
            float Vn   = fmaf(-V[c], G, base) * rcpf_(1.0f + G);

            // ---- rates: 4 independent ex2 off Vn ----
            float dv25 = Vn - 25.0f;
            float dv35 = Vn + 35.0f;
            float eN  = ex2f_(dv25 * c9);
            float eM  = ex2f_(dv35 * c9);
            float eHp = ex2f_( (Vn + 34.0f) * c12);
            float eHm = ex2f_(-(Vn + 34.0f) * c12);

            // branchless singularity patches (reference's exact-equality cases)
            bool sN = (dv25 == 0.0f);
            bool sM = (dv35 == 0.0f);
            float wN = dv25 * rcpf_(eN - 1.0f);
            float wM = dv35 * rcpf_(eM - 1.0f);
            float aN = sN ? 0.18f  : 0.02f  * wN * eN;
            float bN = sN ? 0.08f  : 0.002f * wN;
            float aM = sM ? 1.638f : 0.182f * wM * eM;
            float bM = sM ? 1.16f  : 0.124f * wM;
            float bH = 0.25f * eHp;
            float aH = cAH  * eHm;

            // ---- semi-implicit gates ----
            float pM = 0.01f * (aM + bM);
            float pN = 0.01f * (aN + bN);
            float pH = 0.01f * (aH + bH);
            m[c] = fmaf(aM, 0.02f, fmaf(-pM, m[c], m[c])) * rcpf_(1.0f + pM);
            n[c] = fmaf(aN, 0.02f, fmaf(-pN, n[c], n[c])) * rcpf_(1.0f + pN);
            h[c] = fmaf(aH, 0.02f, fmaf(-pH, h[c], h[c])) * rcpf_(1.0f + pH);
            y[c] = yn;
            V[c] = Vn;

            // ---- output sigmoid (off the recurrence) ----
            float e = ex2f_(-(Vn + 20.0f) * cSIG);
            sg[c] = rcpf_(1.0f + e);
        }

        float4 o; o.x = sg[0]; o.y = sg[1]; o.z = sg[2]; o.w = sg[3];
        *ol = o;
        ol += LQ;
    }
}

extern "C" void kernel_launch(void* const* d_in, const int* in_sizes, int n_in,
                              void* d_out, int out_size) {
    const float4* z = (const float4*)d_in[0];
    float4* out = (float4*)d_out;
    // 16384 chains / 4 per thread = 4096 threads = 128 blocks x 32
    hh_synaptic_kernel<<<128, 32>>>(z, out);
}

// round 5
// speedup vs baseline: 2.9517x; 2.9517x over previous
#include <cuda_runtime.h>
#include <cstdint>

// HH_Synaptic, Round 5: 1 chain/thread (512 warps, best placement) with the
// step body's twin rails (N/M gates) and (h/y) gates packed into f32x2
// (Blackwell FFMA2) to cut per-step instruction count ~40%.

#define N_DIM 2000
#define L_DIM 1024
#define PF    4

__device__ __forceinline__ float ex2f_(float x){ float r; asm("ex2.approx.f32 %0, %1;" : "=f"(r) : "f"(x)); return r; }
__device__ __forceinline__ float rcpf_(float x){ float r; asm("rcp.approx.f32 %0, %1;" : "=f"(r) : "f"(x)); return r; }

__device__ __forceinline__ uint64_t pk2(float lo, float hi){
    uint64_t r; asm("mov.b64 %0, {%1, %2};" : "=l"(r) : "f"(lo), "f"(hi)); return r;
}
__device__ __forceinline__ void upk2(float& lo, float& hi, uint64_t v){
    asm("mov.b64 {%0, %1}, %2;" : "=f"(lo), "=f"(hi) : "l"(v));
}
__device__ __forceinline__ uint64_t fma2_(uint64_t a, uint64_t b, uint64_t c){
    uint64_t d; asm("fma.rn.f32x2 %0, %1, %2, %3;" : "=l"(d) : "l"(a), "l"(b), "l"(c)); return d;
}
__device__ __forceinline__ uint64_t mul2_(uint64_t a, uint64_t b){
    uint64_t d; asm("mul.rn.f32x2 %0, %1, %2;" : "=l"(d) : "l"(a), "l"(b)); return d;
}
__device__ __forceinline__ uint64_t add2_(uint64_t a, uint64_t b){
    uint64_t d; asm("add.rn.f32x2 %0, %1, %2;" : "=l"(d) : "l"(a), "l"(b)); return d;
}

__global__ __launch_bounds__(128, 1)
void hh_synaptic_kernel(const float* __restrict__ z, float* __restrict__ out) {
    const int idx = blockIdx.x * blockDim.x + threadIdx.x;   // 0 .. 16383
    const int b = idx >> 10;
    const int l = idx & (L_DIM - 1);

    const float* zp = z   + (size_t)b * (N_DIM * L_DIM) + l;
    float*       op = out + (size_t)b * (N_DIM * L_DIM) + l;

    const float LOG2E = 1.4426950408889634f;
    const float c9    = LOG2E / 9.0f;
    const float c12   = LOG2E / 12.0f;
    const float cAH   = 0.25f * expf(-56.0f / 12.0f);
    const float cSIG  = LOG2E / 3.0f;

    // Packed constants (lane0 = N-rail, lane1 = M-rail)
    const uint64_t C_off  = pk2(-25.0f, 35.0f);
    const uint64_t C_c9   = pk2(c9, c9);
    const uint64_t C_m1   = pk2(-1.0f, -1.0f);
    const uint64_t C_as   = pk2(0.02f, 0.182f);   // a scale
    const uint64_t C_bs   = pk2(0.002f, 0.124f);  // b scale
    const uint64_t C_001  = pk2(0.01f, 0.01f);
    const uint64_t C_n001 = pk2(-0.01f, -0.01f);
    const uint64_t C_1    = pk2(1.0f, 1.0f);
    const uint64_t C_002  = pk2(0.02f, 0.02f);

    // State: V scalar; (n,m) and (h,y) packed.
    float V = -70.0f;
    uint64_t nm = pk2(0.0f, 0.0f);   // (n, m)
    uint64_t hy = pk2(1.0f, 0.0f);   // (h, y)

    // k = 0 output
    {
        float e = ex2f_(-(V + 20.0f) * cSIG);
        op[0] = rcpf_(1.0f + e);
    }

    // z prefetch ring: step k consumes z index (k-1)
    float zbuf[PF];
    #pragma unroll
    for (int j = 0; j < PF; ++j)
        zbuf[j] = __ldg(zp + (size_t)j * L_DIM);

    float* ol = op + L_DIM;

    #pragma unroll 4
    for (int k = 1; k < N_DIM; ++k) {
        float zc = zbuf[0];
        #pragma unroll
        for (int j = 0; j < PF - 1; ++j) zbuf[j] = zbuf[j + 1];
        int pidx = min(k - 1 + PF, N_DIM - 1);
        zbuf[PF - 1] = __ldg(zp + (size_t)pidx * L_DIM);

        float n_, m_, h_, y_;
        upk2(n_, m_, nm);
        upk2(h_, y_, hy);

        // ---- implicit V update (scalar) ----
        float mm   = m_ * m_;
        float pow1 = (mm * m_) * (40.0f * h_);        // GNA*m^3*h
        float n2   = n_ * n_;
        float pow2 = 35.0f * (n2 * n2);               // GK*n^4
        float G    = 0.01f * ((pow1 + pow2) + (0.3f + y_));
        float E    = fmaf(pow1, 55.0f, fmaf(pow2, -77.0f, -19.5f));
        float base = fmaf(0.02f, E, V + 0.02f);       // V + DT*(E+IAPP)
        float Vn   = fmaf(-V, G, base) * rcpf_(1.0f + G);

        // ---- rate rails packed: lane0 = N (V-25), lane1 = M (V+35) ----
        uint64_t vv  = pk2(Vn, Vn);
        uint64_t dv  = add2_(vv, C_off);              // (dv25, dv35)
        uint64_t ea  = mul2_(dv, C_c9);
        float ealo, eahi; upk2(ealo, eahi, ea);
        float eN = ex2f_(ealo);
        float eM = ex2f_(eahi);
        float eHp = ex2f_(fmaf(Vn,  c12,  34.0f * c12));
        float eHm = ex2f_(fmaf(Vn, -c12, -34.0f * c12));

        uint64_t e2  = pk2(eN, eM);
        uint64_t em1 = add2_(e2, C_m1);               // (eN-1, eM-1)
        float e1lo, e1hi; upk2(e1lo, e1hi, em1);
        uint64_t rw  = pk2(rcpf_(e1lo), rcpf_(e1hi));
        uint64_t w2  = mul2_(dv, rw);                 // (wN, wM)
        uint64_t we  = mul2_(w2, e2);
        uint64_t a2  = mul2_(we, C_as);               // (aN, aM)
        uint64_t b2  = mul2_(w2, C_bs);               // (bN, bM)

        // singularity patches (reference's exact-equality cases)
        float dvlo, dvhi; upk2(dvlo, dvhi, dv);
        float aN, aM, bN, bM;
        upk2(aN, aM, a2); upk2(bN, bM, b2);
        bool sN = (dvlo == 0.0f);
        bool sM = (dvhi == 0.0f);
        aN = sN ? 0.18f  : aN;  bN = sN ? 0.08f : bN;
        aM = sM ? 1.638f : aM;  bM = sM ? 1.16f : bM;
        a2 = pk2(aN, aM); b2 = pk2(bN, bM);

        float aH = cAH * eHm;
        float bH = 0.25f * eHp;

        // ---- gate update (n,m) packed: x' = (0.02a + (1-0.01s)x) * rcp(1+0.01s) ----
        {
            uint64_t s2  = add2_(a2, b2);
            uint64_t dn2 = fma2_(C_001, s2, C_1);
            float dlo, dhi; upk2(dlo, dhi, dn2);
            uint64_t u2  = pk2(rcpf_(dlo), rcpf_(dhi));
            uint64_t np2 = mul2_(s2, C_n001);
            uint64_t t2  = fma2_(np2, nm, nm);
            uint64_t v2  = fma2_(a2, C_002, t2);
            nm = mul2_(v2, u2);
        }
        // ---- gate update (h,y) packed: same form, a=(aH,zc), b=(bH,0.1) ----
        {
            uint64_t ahy = pk2(aH, zc);
            uint64_t bhy = pk2(bH, 0.1f);
            uint64_t s2  = add2_(ahy, bhy);
            uint64_t dn2 = fma2_(C_001, s2, C_1);
            float dlo, dhi; upk2(dlo, dhi, dn2);
            uint64_t u2  = pk2(rcpf_(dlo), rcpf_(dhi));
            uint64_t np2 = mul2_(s2, C_n001);
            uint64_t t2  = fma2_(np2, hy, hy);
            uint64_t v2  = fma2_(ahy, C_002, t2);
            hy = mul2_(v2, u2);
        }

        V = Vn;

        // ---- output sigmoid (off the recurrence) ----
        float e = ex2f_(fmaf(Vn, -cSIG, -20.0f * cSIG));
        *ol = rcpf_(1.0f + e);
        ol += L_DIM;
    }
}

extern "C" void kernel_launch(void* const* d_in, const int* in_sizes, int n_in,
                              void* d_out, int out_size) {
    const float* z = (const float*)d_in[0];
    float* out = (float*)d_out;
    // 16384 threads = 128 blocks x 128: 1 warp per SMSP on 128 SMs (max spread)
    hh_synaptic_kernel<<<128, 128>>>(z, out);
}

// round 6
// speedup vs baseline: 3.4215x; 1.1592x over previous
#include <cuda_runtime.h>
#include <cstdint>

// HH_Synaptic, Round 6: fused gate algebra — one rcp per gate rail instead of
// two: x' = (0.02*s*dv*e + x*(D-q)) / (D+q), D=e-1, q=0.01*dv*(s*e+t).
// N/M rails packed f32x2; singularity patch via constant-FMA select;
// y-gate rcp replaced by 3-FMA series (p <= 0.011).

#define N_DIM 2000
#define L_DIM 1024
#define PF    4

__device__ __forceinline__ float ex2f_(float x){ float r; asm("ex2.approx.f32 %0, %1;" : "=f"(r) : "f"(x)); return r; }
__device__ __forceinline__ float rcpf_(float x){ float r; asm("rcp.approx.f32 %0, %1;" : "=f"(r) : "f"(x)); return r; }

__device__ __forceinline__ uint64_t pk2(float lo, float hi){
    uint64_t r; asm("mov.b64 %0, {%1, %2};" : "=l"(r) : "f"(lo), "f"(hi)); return r;
}
__device__ __forceinline__ void upk2(float& lo, float& hi, uint64_t v){
    asm("mov.b64 {%0, %1}, %2;" : "=f"(lo), "=f"(hi) : "l"(v));
}
__device__ __forceinline__ uint64_t fma2_(uint64_t a, uint64_t b, uint64_t c){
    uint64_t d; asm("fma.rn.f32x2 %0, %1, %2, %3;" : "=l"(d) : "l"(a), "l"(b), "l"(c)); return d;
}
__device__ __forceinline__ uint64_t mul2_(uint64_t a, uint64_t b){
    uint64_t d; asm("mul.rn.f32x2 %0, %1, %2;" : "=l"(d) : "l"(a), "l"(b)); return d;
}
__device__ __forceinline__ uint64_t add2_(uint64_t a, uint64_t b){
    uint64_t d; asm("add.rn.f32x2 %0, %1, %2;" : "=l"(d) : "l"(a), "l"(b)); return d;
}

__global__ __launch_bounds__(128, 1)
void hh_synaptic_kernel(const float* __restrict__ z, float* __restrict__ out) {
    const int idx = blockIdx.x * blockDim.x + threadIdx.x;   // 0 .. 16383
    const int b = idx >> 10;
    const int l = idx & (L_DIM - 1);

    const float* zp = z   + (size_t)b * (N_DIM * L_DIM) + l;
    float*       op = out + (size_t)b * (N_DIM * L_DIM) + l;

    const float LOG2E = 1.4426950408889634f;
    const float c9    = LOG2E / 9.0f;
    const float c12   = LOG2E / 12.0f;
    const float cAH   = 0.25f * expf(-56.0f / 12.0f);
    const float cSIG  = LOG2E / 3.0f;

    // Packed constants (lane0 = N-rail, lane1 = M-rail)
    const uint64_t C_off  = pk2(-25.0f, 35.0f);
    const uint64_t C_c9   = pk2(c9, c9);
    const uint64_t C_m1   = pk2(-1.0f, -1.0f);
    const uint64_t C_se   = pk2(0.02f, 0.182f);     // s (e-coefficient in s*e+t)
    const uint64_t C_t    = pk2(0.002f, 0.124f);    // t
    const uint64_t C_sc   = pk2(0.02f*0.02f, 0.02f*0.182f); // 0.02*s for numerator
    const uint64_t C_001  = pk2(0.01f, 0.01f);

    // Singularity-patch constants: x' = kP*x + cP (one FMA)
    const float pN_ = 0.01f*(0.18f+0.08f),  pM_ = 0.01f*(1.638f+1.16f);
    const float kNp = (1.0f-pN_)/(1.0f+pN_), cNp = (0.02f*0.18f)/(1.0f+pN_);
    const float kMp = (1.0f-pM_)/(1.0f+pM_), cMp = (0.02f*1.638f)/(1.0f+pM_);

    // State: V scalar; (n,m) packed; h,y scalar.
    float V = -70.0f;
    uint64_t nm = pk2(0.0f, 0.0f);   // (n, m)
    float h = 1.0f, y = 0.0f;

    // k = 0 output
    {
        float e = ex2f_(-(V + 20.0f) * cSIG);
        op[0] = rcpf_(1.0f + e);
    }

    // z prefetch ring: step k consumes z index (k-1)
    float zbuf[PF];
    #pragma unroll
    for (int j = 0; j < PF; ++j)
        zbuf[j] = __ldg(zp + (size_t)j * L_DIM);

    float* ol = op + L_DIM;

    #pragma unroll 4
    for (int k = 1; k < N_DIM; ++k) {
        float zc = zbuf[0];
        #pragma unroll
        for (int j = 0; j < PF - 1; ++j) zbuf[j] = zbuf[j + 1];
        int pidx = min(k - 1 + PF, N_DIM - 1);
        zbuf[PF - 1] = __ldg(zp + (size_t)pidx * L_DIM);

        float n_, m_;
        upk2(n_, m_, nm);

        // ---- y update (independent of V path): rcp via series, p <= 0.011 ----
        float pY = fmaf(0.01f, zc, 0.001f);
        float rY = fmaf(pY, fmaf(pY, 1.0f - pY, -1.0f), 1.0f);  // 1 - p + p^2 - p^3
        float yn = fmaf(zc, 0.02f, fmaf(-pY, y, y)) * rY;

        // ---- implicit V update ----
        float mm   = m_ * m_;
        float pow1 = (mm * m_) * (40.0f * h);            // GNA*m^3*h
        float n2   = n_ * n_;
        float pow2 = 35.0f * (n2 * n2);                  // GK*n^4
        float G    = 0.01f * ((pow1 + pow2) + (0.3f + y));
        float E    = fmaf(pow1, 55.0f, fmaf(pow2, -77.0f, -19.5f));
        float base = fmaf(0.02f, E, V + 0.02f);          // V + DT*(E+IAPP)
        float Vn   = fmaf(-V, G, base) * rcpf_(1.0f + G);

        // ---- N/M rails, fused single-rcp form ----
        uint64_t vv   = pk2(Vn, Vn);
        uint64_t dv2  = add2_(vv, C_off);                // (dv25, dv35)
        uint64_t dv01 = mul2_(dv2, C_001);               // 0.01*dv (parallel to ex2)
        uint64_t ea2  = mul2_(dv2, C_c9);
        float ealo, eahi; upk2(ealo, eahi, ea2);
        float eN = ex2f_(ealo);
        float eM = ex2f_(eahi);
        float eHp = ex2f_(fmaf(Vn,  c12,  34.0f * c12));
        float eHm = ex2f_(fmaf(Vn, -c12, -34.0f * c12));

        uint64_t e2   = pk2(eN, eM);
        uint64_t D2   = add2_(e2, C_m1);                 // e - 1
        uint64_t set2 = fma2_(C_se, e2, C_t);            // s*e + t
        uint64_t q2   = mul2_(dv01, set2);               // q = 0.01*dv*(s*e+t)
        uint64_t Dq2  = add2_(D2, q2);                   // D + q
        float dqlo, dqhi; upk2(dqlo, dqhi, Dq2);
        uint64_t r2   = pk2(rcpf_(dqlo), rcpf_(dqhi));   // rcp(D+q)
        uint64_t Dmq2 = fma2_(q2, C_m1, D2);             // D - q
        uint64_t edv2 = mul2_(e2, dv2);                  // e*dv
        uint64_t num2 = fma2_(nm, Dmq2, mul2_(edv2, C_sc)); // x*(D-q) + 0.02*s*dv*e
        uint64_t res2 = mul2_(num2, r2);

        // singularity patches (reference's exact-equality cases; fused form NaNs at dv=0)
        float dvlo, dvhi; upk2(dvlo, dvhi, dv2);
        float rn, rm; upk2(rn, rm, res2);
        rn = (dvlo == 0.0f) ? fmaf(n_, kNp, cNp) : rn;
        rm = (dvhi == 0.0f) ? fmaf(m_, kMp, cMp) : rm;
        nm = pk2(rn, rm);

        // ---- h gate (standard, one rcp) ----
        float aH = cAH  * eHm;
        float bH = 0.25f * eHp;
        float pH = 0.01f * (aH + bH);
        h = fmaf(aH, 0.02f, fmaf(-pH, h, h)) * rcpf_(1.0f + pH);
        y = yn;
        V = Vn;

        // ---- output sigmoid (off the recurrence) ----
        float e = ex2f_(fmaf(Vn, -cSIG, -20.0f * cSIG));
        *ol = rcpf_(1.0f + e);
        ol += L_DIM;
    }
}

extern "C" void kernel_launch(void* const* d_in, const int* in_sizes, int n_in,
                              void* d_out, int out_size) {
    const float* z = (const float*)d_in[0];
    float* out = (float*)d_out;
    // 16384 threads = 128 blocks x 128: 1 warp per SMSP on 128 SMs
    hh_synaptic_kernel<<<128, 128>>>(z, out);
}